// round 10
// baseline (speedup 1.0000x reference)
#include <cuda_runtime.h>
#include <cuda_fp16.h>
#include <cstdint>

#define N_NODES 50000
#define N_EDGES 800000
#define F 64
#define TILE_M 128
#define ROW_STRIDE 132      // f32 stride of staged rows
#define WS_STRIDE 72        // float2 stride of W hi/lo in smem

// Scratch (allocation-free: __device__ globals)
__device__ int    g_deg[N_NODES];        // invariant: zero at kernel_launch entry
__device__ int    g_off[N_NODES + 1];
__device__ int    g_cur[N_NODES];
__device__ int    g_csr[N_EDGES];
__device__ float  g_h[N_NODES * F];
__device__ float  g_agg[N_NODES * F];
__device__ __half g_half[N_NODES * F];   // fp16 mirror of gather source
__device__ float2 g_ws1[128 * 64];       // W1 hi/lo split (3xTF32)
__device__ float2 g_ws2[128 * 64];       // W2 hi/lo split
__device__ int    g_is64;

__device__ __forceinline__ int detect_is64(const void* ei) {
    const long long* p64 = (const long long*)ei;
    int ok = 1;
    #pragma unroll
    for (int j = 0; j < 16; j++) {
        long long v = p64[j];
        if (v < 0 || v >= N_NODES) ok = 0;
    }
    return ok;
}

__device__ __forceinline__ int load_idx(const void* ei, int i, int is64) {
    if (is64) return (int)((const long long*)ei)[i];
    return ((const int*)ei)[i];
}

__device__ __forceinline__ unsigned tf32_hi(float a) {
    unsigned r;
    asm("cvt.rna.tf32.f32 %0, %1;" : "=r"(r) : "f"(a));
    return r;
}

// ---------------------------------------------------------------------------
// Prep (one kernel): dtype detect + x->fp16 convert + degree histogram +
// W1/W2 hi/lo split. Requires g_deg == 0 on entry (module init / scan kernel
// restores it each call).
// ---------------------------------------------------------------------------
__global__ void prep_kernel(const void* __restrict__ ei,
                            const float* __restrict__ x,
                            const float* __restrict__ W1,
                            const float* __restrict__ W2) {
    int i = blockIdx.x * blockDim.x + threadIdx.x;
    int is64 = detect_is64(ei);            // uniform, L1-cached
    if (i == 0) g_is64 = is64;

    if (i < N_NODES * F / 2) {
        float2 v = ((const float2*)x)[i];
        ((__half2*)g_half)[i] = __floats2half2_rn(v.x, v.y);
    }
    if (i < N_EDGES) {
        int d = load_idx(ei, N_EDGES + i, is64);
        if ((unsigned)d < N_NODES) atomicAdd(&g_deg[d], 1);
    }
    if (i < 2 * 128 * 64) {
        const float* Wsel = (i < 128 * 64) ? W1 : W2;
        float2* dst = (i < 128 * 64) ? g_ws1 : g_ws2;
        int idx = i & (128 * 64 - 1);
        float w = Wsel[idx];
        unsigned hb = tf32_hi(w);
        float hf = __uint_as_float(hb);
        unsigned lb = tf32_hi(w - hf);
        dst[idx] = make_float2(hf, __uint_as_float(lb));
    }
}

// ---------------------------------------------------------------------------
// Single-kernel exclusive scan of degrees -> g_off, plus re-zero g_deg
// (restores prep precondition) and zero g_cur (fill precondition).
// One block, 1024 threads, 49 tiles, shfl block-scan.
// ---------------------------------------------------------------------------
__global__ void __launch_bounds__(1024)
scan_kernel() {
    __shared__ int warp_sums[32];
    int tid = threadIdx.x;
    int lane = tid & 31, wid = tid >> 5;
    int carry = 0;

    for (int base = 0; base < N_NODES; base += 1024) {
        int i = base + tid;
        int v = (i < N_NODES) ? g_deg[i] : 0;
        // inclusive warp scan
        int s = v;
        #pragma unroll
        for (int o = 1; o < 32; o <<= 1) {
            int t = __shfl_up_sync(0xffffffffu, s, o);
            if (lane >= o) s += t;
        }
        if (lane == 31) warp_sums[wid] = s;
        __syncthreads();
        if (wid == 0) {
            int ws = warp_sums[lane];
            #pragma unroll
            for (int o = 1; o < 32; o <<= 1) {
                int t = __shfl_up_sync(0xffffffffu, ws, o);
                if (lane >= o) ws += t;
            }
            warp_sums[lane] = ws;
        }
        __syncthreads();
        int incl = s + (wid > 0 ? warp_sums[wid - 1] : 0) + carry;
        if (i < N_NODES) {
            g_off[i + 1] = incl;
            g_deg[i] = 0;      // restore invariant for next call
            g_cur[i] = 0;      // fill precondition
        }
        carry += warp_sums[31];
        __syncthreads();       // protect warp_sums before next tile
    }
    if (tid == 0) g_off[0] = 0;
}

// ---------------------------------------------------------------------------
__global__ void fill_kernel(const void* __restrict__ ei) {
    int e = blockIdx.x * blockDim.x + threadIdx.x;
    if (e >= N_EDGES) return;
    int is64 = g_is64;
    int s = load_idx(ei, e, is64);
    int d = load_idx(ei, N_EDGES + e, is64);
    if ((unsigned)s >= N_NODES || (unsigned)d >= N_NODES) return;
    int pos = atomicAdd(&g_cur[d], 1);
    g_csr[g_off[d] + pos] = s;
}

// ---------------------------------------------------------------------------
// CSR mean-aggregation from fp16 mirror -> g_agg (f32).
// One node per warp, unroll-8 edge loop (high MLP).
// ---------------------------------------------------------------------------
__global__ void __launch_bounds__(256)
agg_kernel() {
    int warp = threadIdx.x >> 5, lane = threadIdx.x & 31;
    int n = blockIdx.x * 8 + warp;
    if (n >= N_NODES) return;
    const __half2* xh2 = (const __half2*)g_half;

    int e0 = g_off[n], e1 = g_off[n + 1];
    float ax = 0.f, ay = 0.f;
    int e = e0;
    for (; e + 8 <= e1; e += 8) {
        int s0 = g_csr[e],     s1 = g_csr[e + 1];
        int s2 = g_csr[e + 2], s3 = g_csr[e + 3];
        int s4 = g_csr[e + 4], s5 = g_csr[e + 5];
        int s6 = g_csr[e + 6], s7 = g_csr[e + 7];
        __half2 h0 = xh2[s0 * 32 + lane];
        __half2 h1 = xh2[s1 * 32 + lane];
        __half2 h2 = xh2[s2 * 32 + lane];
        __half2 h3 = xh2[s3 * 32 + lane];
        __half2 h4 = xh2[s4 * 32 + lane];
        __half2 h5 = xh2[s5 * 32 + lane];
        __half2 h6 = xh2[s6 * 32 + lane];
        __half2 h7 = xh2[s7 * 32 + lane];
        float2 v0 = __half22float2(h0), v1 = __half22float2(h1);
        float2 v2 = __half22float2(h2), v3 = __half22float2(h3);
        float2 v4 = __half22float2(h4), v5 = __half22float2(h5);
        float2 v6 = __half22float2(h6), v7 = __half22float2(h7);
        ax += (v0.x + v1.x) + (v2.x + v3.x) + (v4.x + v5.x) + (v6.x + v7.x);
        ay += (v0.y + v1.y) + (v2.y + v3.y) + (v4.y + v5.y) + (v6.y + v7.y);
    }
    for (; e < e1; e++) {
        float2 v = __half22float2(xh2[g_csr[e] * 32 + lane]);
        ax += v.x; ay += v.y;
    }
    float inv = 1.0f / fmaxf((float)(e1 - e0), 1.0f);
    ((float2*)g_agg)[n * 32 + lane] = make_float2(ax * inv, ay * inv);
}

// ---------------------------------------------------------------------------
// Tensor-core GEMM (3xTF32): out = [x || agg] @ W + b (+ReLU)
// W hi/lo pre-split in global; staged to smem with float4 copies.
// ---------------------------------------------------------------------------
__device__ __forceinline__ void mma_tf32(float* c, unsigned a0, unsigned a1,
                                         unsigned a2, unsigned a3,
                                         unsigned b0, unsigned b1) {
    asm volatile(
        "mma.sync.aligned.m16n8k8.row.col.f32.tf32.tf32.f32 "
        "{%0,%1,%2,%3}, {%4,%5,%6,%7}, {%8,%9}, {%0,%1,%2,%3};"
        : "+f"(c[0]), "+f"(c[1]), "+f"(c[2]), "+f"(c[3])
        : "r"(a0), "r"(a1), "r"(a2), "r"(a3), "r"(b0), "r"(b1));
}

__global__ void __launch_bounds__(256)
gemm_kernel(const float* __restrict__ xin, const float2* __restrict__ Wsplit,
            const float* __restrict__ bias, float* __restrict__ out,
            int relu, int to_half) {
    extern __shared__ float sm[];
    float*  row = sm;                                   // [128][132] f32
    float2* Ws2 = (float2*)(sm + TILE_M * ROW_STRIDE);  // [128][72] (hi,lo)

    int tid = threadIdx.x;

    // Stage pre-split W: 4096 float4, 16 per thread, into padded layout.
    const float4* wsrc = (const float4*)Wsplit;
    #pragma unroll
    for (int i = 0; i < 16; i++) {
        int j = tid + i * 256;        // float4 index 0..4095
        int f2 = j * 2;               // float2 index
        int k = f2 >> 6, c = f2 & 63;
        *(float4*)&Ws2[k * WS_STRIDE + c] = wsrc[j];
    }

    int base = blockIdx.x * TILE_M;
    #pragma unroll
    for (int i = 0; i < 8; i++) {
        int idx = tid + i * 256;
        int nl = idx >> 4, q = idx & 15;
        int n = base + nl;
        int nc = n < N_NODES ? n : N_NODES - 1;
        float4 xv = ((const float4*)xin)[nc * 16 + q];
        *(float4*)&row[nl * ROW_STRIDE + q * 4] = xv;
        float4 av = ((const float4*)g_agg)[nc * 16 + q];
        *(float4*)&row[nl * ROW_STRIDE + 64 + q * 4] = av;
    }
    __syncthreads();

    int warp = tid >> 5, lane = tid & 31;
    int g = lane >> 2, t = lane & 3;
    int r0 = warp * 16 + g;

    float acc[8][4];
    #pragma unroll
    for (int nt = 0; nt < 8; nt++) {
        float2 bv = ((const float2*)bias)[nt * 4 + t];
        acc[nt][0] = bv.x; acc[nt][1] = bv.y;
        acc[nt][2] = bv.x; acc[nt][3] = bv.y;
    }

    #pragma unroll 2
    for (int ks = 0; ks < 16; ks++) {
        int k0 = ks * 8;
        float a0f = row[r0 * ROW_STRIDE + k0 + t];
        float a1f = row[(r0 + 8) * ROW_STRIDE + k0 + t];
        float a2f = row[r0 * ROW_STRIDE + k0 + t + 4];
        float a3f = row[(r0 + 8) * ROW_STRIDE + k0 + t + 4];
        unsigned ah0 = tf32_hi(a0f), ah1 = tf32_hi(a1f);
        unsigned ah2 = tf32_hi(a2f), ah3 = tf32_hi(a3f);
        unsigned al0 = tf32_hi(a0f - __uint_as_float(ah0));
        unsigned al1 = tf32_hi(a1f - __uint_as_float(ah1));
        unsigned al2 = tf32_hi(a2f - __uint_as_float(ah2));
        unsigned al3 = tf32_hi(a3f - __uint_as_float(ah3));

        #pragma unroll
        for (int nt = 0; nt < 8; nt++) {
            float2 w0 = Ws2[(k0 + t)     * WS_STRIDE + nt * 8 + g];
            float2 w1 = Ws2[(k0 + t + 4) * WS_STRIDE + nt * 8 + g];
            unsigned bh0 = __float_as_uint(w0.x), bl0 = __float_as_uint(w0.y);
            unsigned bh1 = __float_as_uint(w1.x), bl1 = __float_as_uint(w1.y);
            mma_tf32(acc[nt], ah0, ah1, ah2, ah3, bh0, bh1);
            mma_tf32(acc[nt], ah0, ah1, ah2, ah3, bl0, bl1);
            mma_tf32(acc[nt], al0, al1, al2, al3, bh0, bh1);
        }
    }

    int n0 = base + r0;
    int n1 = n0 + 8;
    float2*  out2 = (float2*)out;
    __half2* oh2  = (__half2*)g_half;
    #pragma unroll
    for (int nt = 0; nt < 8; nt++) {
        float c0 = acc[nt][0], c1 = acc[nt][1];
        float c2 = acc[nt][2], c3 = acc[nt][3];
        if (relu) {
            c0 = fmaxf(c0, 0.f); c1 = fmaxf(c1, 0.f);
            c2 = fmaxf(c2, 0.f); c3 = fmaxf(c3, 0.f);
        }
        int colp = nt * 4 + t;
        if (n0 < N_NODES) {
            out2[n0 * 32 + colp] = make_float2(c0, c1);
            if (to_half) oh2[n0 * 32 + colp] = __floats2half2_rn(c0, c1);
        }
        if (n1 < N_NODES) {
            out2[n1 * 32 + colp] = make_float2(c2, c3);
            if (to_half) oh2[n1 * 32 + colp] = __floats2half2_rn(c2, c3);
        }
    }
}

// ---------------------------------------------------------------------------
extern "C" void kernel_launch(void* const* d_in, const int* in_sizes, int n_in,
                              void* d_out, int out_size) {
    const float* x   = (const float*)d_in[0];
    const void*  ei  = d_in[1];
    const float* W1  = (const float*)d_in[2];
    const float* b1  = (const float*)d_in[3];
    const float* W2  = (const float*)d_in[4];
    const float* b2  = (const float*)d_in[5];
    float*       out = (float*)d_out;

    float*  hbuf = nullptr;
    float2* ws1  = nullptr;
    float2* ws2  = nullptr;
    cudaGetSymbolAddress((void**)&hbuf, g_h);
    cudaGetSymbolAddress((void**)&ws1, g_ws1);
    cudaGetSymbolAddress((void**)&ws2, g_ws2);

    const int PREP_BLOCKS = (N_NODES * F / 2 + 255) / 256;       // 6250
    const int EDGE_BLOCKS = (N_EDGES + 255) / 256;               // 3125
    const int AGG_BLOCKS  = (N_NODES + 7) / 8;                   // 6250
    const int GEMM_BLOCKS = (N_NODES + TILE_M - 1) / TILE_M;     // 391
    const int SMEM_BYTES  = (TILE_M * ROW_STRIDE) * 4 + 128 * WS_STRIDE * 8;

    cudaFuncSetAttribute(gemm_kernel,
                         cudaFuncAttributeMaxDynamicSharedMemorySize, SMEM_BYTES);

    prep_kernel<<<PREP_BLOCKS, 256>>>(ei, x, W1, W2);
    scan_kernel<<<1, 1024>>>();
    fill_kernel<<<EDGE_BLOCKS, 256>>>(ei);

    // Layer 1
    agg_kernel<<<AGG_BLOCKS, 256>>>();
    gemm_kernel<<<GEMM_BLOCKS, 256, SMEM_BYTES>>>(x, ws1, b1, hbuf,
                                                  /*relu=*/1, /*to_half=*/1);
    // Layer 2
    agg_kernel<<<AGG_BLOCKS, 256>>>();
    gemm_kernel<<<GEMM_BLOCKS, 256, SMEM_BYTES>>>(hbuf, ws2, b2, out,
                                                  /*relu=*/0, /*to_half=*/0);
}

// round 11
// speedup vs baseline: 1.2943x; 1.2943x over previous
#include <cuda_runtime.h>
#include <cuda_fp16.h>
#include <cstdint>

#define N_NODES 50000
#define N_EDGES 800000
#define F 64
#define TILE_M 128
#define ROW_STRIDE 132      // f32 stride of staged rows
#define WS_STRIDE 72        // float2 stride of W hi/lo in smem
#define SCAN_BLOCKS 196

// Scratch (allocation-free: __device__ globals)
__device__ int    g_deg[N_NODES];
__device__ int    g_off[N_NODES + 1];
__device__ int    g_cur[N_NODES];
__device__ int    g_csr[N_EDGES];
__device__ int    g_bsum[SCAN_BLOCKS];
__device__ float  g_h[N_NODES * F];
__device__ float  g_agg[N_NODES * F];
__device__ __half g_half[N_NODES * F];   // fp16 mirror of gather source
__device__ float2 g_ws1[128 * 64];       // W1 hi/lo split (3xTF32)
__device__ float2 g_ws2[128 * 64];       // W2 hi/lo split
__device__ int    g_is64;

__device__ __forceinline__ int load_idx(const void* ei, int i, int is64) {
    if (is64) return (int)((const long long*)ei)[i];
    return ((const int*)ei)[i];
}

__device__ __forceinline__ unsigned tf32_hi(float a) {
    unsigned r;
    asm("cvt.rna.tf32.f32 %0, %1;" : "=r"(r) : "f"(a));
    return r;
}

// ---------------------------------------------------------------------------
// Prep: dtype detect (thread 0 only) + zero degree + x->fp16 mirror +
// W1/W2 hi/lo split (3xTF32 precompute).
// ---------------------------------------------------------------------------
__global__ void prep_kernel(const void* __restrict__ ei,
                            const float* __restrict__ x,
                            const float* __restrict__ W1,
                            const float* __restrict__ W2) {
    int i = blockIdx.x * blockDim.x + threadIdx.x;
    if (i == 0) {
        const long long* p64 = (const long long*)ei;
        int ok = 1;
        #pragma unroll
        for (int j = 0; j < 16; j++) {
            long long v = p64[j];
            if (v < 0 || v >= N_NODES) ok = 0;
        }
        g_is64 = ok;
    }
    if (i < N_NODES) g_deg[i] = 0;
    if (i < N_NODES * F / 2) {
        float2 v = ((const float2*)x)[i];
        ((__half2*)g_half)[i] = __floats2half2_rn(v.x, v.y);
    }
    if (i < 2 * 128 * 64) {
        const float* Wsel = (i < 128 * 64) ? W1 : W2;
        float2* dst = (i < 128 * 64) ? g_ws1 : g_ws2;
        int idx = i & (128 * 64 - 1);
        float w = Wsel[idx];
        unsigned hb = tf32_hi(w);
        float hf = __uint_as_float(hb);
        unsigned lb = tf32_hi(w - hf);
        dst[idx] = make_float2(hf, __uint_as_float(lb));
    }
}

// ---------------------------------------------------------------------------
// CSR build: histogram -> scan1 -> scan23 -> fill (parallel, proven in R9)
// ---------------------------------------------------------------------------
__global__ void hist_kernel(const void* __restrict__ ei) {
    int e = blockIdx.x * blockDim.x + threadIdx.x;
    if (e >= N_EDGES) return;
    int d = load_idx(ei, N_EDGES + e, g_is64);
    if ((unsigned)d < N_NODES) atomicAdd(&g_deg[d], 1);
}

__global__ void scan1_kernel() {
    __shared__ int sh[256];
    int t = threadIdx.x;
    int i = blockIdx.x * 256 + t;
    int v = (i < N_NODES) ? g_deg[i] : 0;
    sh[t] = v;
    __syncthreads();
    #pragma unroll
    for (int ofs = 1; ofs < 256; ofs <<= 1) {
        int add = (t >= ofs) ? sh[t - ofs] : 0;
        __syncthreads();
        sh[t] += add;
        __syncthreads();
    }
    if (i < N_NODES) g_off[i + 1] = sh[t];
    if (t == 255) g_bsum[blockIdx.x] = sh[255];
}

__global__ void scan23_kernel() {
    __shared__ int sh[256];
    int t = threadIdx.x;
    sh[t] = (t < SCAN_BLOCKS) ? g_bsum[t] : 0;
    __syncthreads();
    #pragma unroll
    for (int ofs = 1; ofs < 256; ofs <<= 1) {
        int add = (t >= ofs) ? sh[t - ofs] : 0;
        __syncthreads();
        sh[t] += add;
        __syncthreads();
    }
    int prefix = (blockIdx.x > 0) ? sh[blockIdx.x - 1] : 0;
    int i = blockIdx.x * 256 + t;
    if (i < N_NODES) {
        g_off[i + 1] += prefix;
        g_cur[i] = 0;
    }
    if (i == 0) g_off[0] = 0;
}

__global__ void fill_kernel(const void* __restrict__ ei) {
    int e = blockIdx.x * blockDim.x + threadIdx.x;
    if (e >= N_EDGES) return;
    int is64 = g_is64;
    int s = load_idx(ei, e, is64);
    int d = load_idx(ei, N_EDGES + e, is64);
    if ((unsigned)s >= N_NODES || (unsigned)d >= N_NODES) return;
    int pos = atomicAdd(&g_cur[d], 1);
    g_csr[g_off[d] + pos] = s;
}

// ---------------------------------------------------------------------------
// CSR mean-aggregation from fp16 mirror -> g_agg (f32).
// One node per warp, unroll-8 edge loop (high MLP). Proven at 20.7us in R10.
// ---------------------------------------------------------------------------
__global__ void __launch_bounds__(256)
agg_kernel() {
    int warp = threadIdx.x >> 5, lane = threadIdx.x & 31;
    int n = blockIdx.x * 8 + warp;
    if (n >= N_NODES) return;
    const __half2* xh2 = (const __half2*)g_half;

    int e0 = g_off[n], e1 = g_off[n + 1];
    float ax = 0.f, ay = 0.f;
    int e = e0;
    for (; e + 8 <= e1; e += 8) {
        int s0 = g_csr[e],     s1 = g_csr[e + 1];
        int s2 = g_csr[e + 2], s3 = g_csr[e + 3];
        int s4 = g_csr[e + 4], s5 = g_csr[e + 5];
        int s6 = g_csr[e + 6], s7 = g_csr[e + 7];
        __half2 h0 = xh2[s0 * 32 + lane];
        __half2 h1 = xh2[s1 * 32 + lane];
        __half2 h2 = xh2[s2 * 32 + lane];
        __half2 h3 = xh2[s3 * 32 + lane];
        __half2 h4 = xh2[s4 * 32 + lane];
        __half2 h5 = xh2[s5 * 32 + lane];
        __half2 h6 = xh2[s6 * 32 + lane];
        __half2 h7 = xh2[s7 * 32 + lane];
        float2 v0 = __half22float2(h0), v1 = __half22float2(h1);
        float2 v2 = __half22float2(h2), v3 = __half22float2(h3);
        float2 v4 = __half22float2(h4), v5 = __half22float2(h5);
        float2 v6 = __half22float2(h6), v7 = __half22float2(h7);
        ax += (v0.x + v1.x) + (v2.x + v3.x) + (v4.x + v5.x) + (v6.x + v7.x);
        ay += (v0.y + v1.y) + (v2.y + v3.y) + (v4.y + v5.y) + (v6.y + v7.y);
    }
    for (; e < e1; e++) {
        float2 v = __half22float2(xh2[g_csr[e] * 32 + lane]);
        ax += v.x; ay += v.y;
    }
    float inv = 1.0f / fmaxf((float)(e1 - e0), 1.0f);
    ((float2*)g_agg)[n * 32 + lane] = make_float2(ax * inv, ay * inv);
}

// ---------------------------------------------------------------------------
// Tensor-core GEMM (3xTF32): out = [x || agg] @ W + b (+ReLU)
// W hi/lo pre-split in global; staged to smem with float4 copies.
// ---------------------------------------------------------------------------
__device__ __forceinline__ void mma_tf32(float* c, unsigned a0, unsigned a1,
                                         unsigned a2, unsigned a3,
                                         unsigned b0, unsigned b1) {
    asm volatile(
        "mma.sync.aligned.m16n8k8.row.col.f32.tf32.tf32.f32 "
        "{%0,%1,%2,%3}, {%4,%5,%6,%7}, {%8,%9}, {%0,%1,%2,%3};"
        : "+f"(c[0]), "+f"(c[1]), "+f"(c[2]), "+f"(c[3])
        : "r"(a0), "r"(a1), "r"(a2), "r"(a3), "r"(b0), "r"(b1));
}

__global__ void __launch_bounds__(256)
gemm_kernel(const float* __restrict__ xin, const float2* __restrict__ Wsplit,
            const float* __restrict__ bias, float* __restrict__ out,
            int relu, int to_half) {
    extern __shared__ float sm[];
    float*  row = sm;                                   // [128][132] f32
    float2* Ws2 = (float2*)(sm + TILE_M * ROW_STRIDE);  // [128][72] (hi,lo)

    int tid = threadIdx.x;

    // Stage pre-split W: 4096 float4 (= 8192 float2), 16 per thread.
    const float4* wsrc = (const float4*)Wsplit;
    #pragma unroll
    for (int i = 0; i < 16; i++) {
        int j = tid + i * 256;        // float4 index 0..4095
        int f2 = j * 2;               // float2 index
        int k = f2 >> 6, c = f2 & 63;
        *(float4*)&Ws2[k * WS_STRIDE + c] = wsrc[j];
    }

    int base = blockIdx.x * TILE_M;
    #pragma unroll
    for (int i = 0; i < 8; i++) {
        int idx = tid + i * 256;
        int nl = idx >> 4, q = idx & 15;
        int n = base + nl;
        int nc = n < N_NODES ? n : N_NODES - 1;
        float4 xv = ((const float4*)xin)[nc * 16 + q];
        *(float4*)&row[nl * ROW_STRIDE + q * 4] = xv;
        float4 av = ((const float4*)g_agg)[nc * 16 + q];
        *(float4*)&row[nl * ROW_STRIDE + 64 + q * 4] = av;
    }
    __syncthreads();

    int warp = tid >> 5, lane = tid & 31;
    int g = lane >> 2, t = lane & 3;
    int r0 = warp * 16 + g;

    float acc[8][4];
    #pragma unroll
    for (int nt = 0; nt < 8; nt++) {
        float2 bv = ((const float2*)bias)[nt * 4 + t];
        acc[nt][0] = bv.x; acc[nt][1] = bv.y;
        acc[nt][2] = bv.x; acc[nt][3] = bv.y;
    }

    #pragma unroll 2
    for (int ks = 0; ks < 16; ks++) {
        int k0 = ks * 8;
        float a0f = row[r0 * ROW_STRIDE + k0 + t];
        float a1f = row[(r0 + 8) * ROW_STRIDE + k0 + t];
        float a2f = row[r0 * ROW_STRIDE + k0 + t + 4];
        float a3f = row[(r0 + 8) * ROW_STRIDE + k0 + t + 4];
        unsigned ah0 = tf32_hi(a0f), ah1 = tf32_hi(a1f);
        unsigned ah2 = tf32_hi(a2f), ah3 = tf32_hi(a3f);
        unsigned al0 = tf32_hi(a0f - __uint_as_float(ah0));
        unsigned al1 = tf32_hi(a1f - __uint_as_float(ah1));
        unsigned al2 = tf32_hi(a2f - __uint_as_float(ah2));
        unsigned al3 = tf32_hi(a3f - __uint_as_float(ah3));

        #pragma unroll
        for (int nt = 0; nt < 8; nt++) {
            float2 w0 = Ws2[(k0 + t)     * WS_STRIDE + nt * 8 + g];
            float2 w1 = Ws2[(k0 + t + 4) * WS_STRIDE + nt * 8 + g];
            unsigned bh0 = __float_as_uint(w0.x), bl0 = __float_as_uint(w0.y);
            unsigned bh1 = __float_as_uint(w1.x), bl1 = __float_as_uint(w1.y);
            mma_tf32(acc[nt], ah0, ah1, ah2, ah3, bh0, bh1);
            mma_tf32(acc[nt], ah0, ah1, ah2, ah3, bl0, bl1);
            mma_tf32(acc[nt], al0, al1, al2, al3, bh0, bh1);
        }
    }

    int n0 = base + r0;
    int n1 = n0 + 8;
    float2*  out2 = (float2*)out;
    __half2* oh2  = (__half2*)g_half;
    #pragma unroll
    for (int nt = 0; nt < 8; nt++) {
        float c0 = acc[nt][0], c1 = acc[nt][1];
        float c2 = acc[nt][2], c3 = acc[nt][3];
        if (relu) {
            c0 = fmaxf(c0, 0.f); c1 = fmaxf(c1, 0.f);
            c2 = fmaxf(c2, 0.f); c3 = fmaxf(c3, 0.f);
        }
        int colp = nt * 4 + t;
        if (n0 < N_NODES) {
            out2[n0 * 32 + colp] = make_float2(c0, c1);
            if (to_half) oh2[n0 * 32 + colp] = __floats2half2_rn(c0, c1);
        }
        if (n1 < N_NODES) {
            out2[n1 * 32 + colp] = make_float2(c2, c3);
            if (to_half) oh2[n1 * 32 + colp] = __floats2half2_rn(c2, c3);
        }
    }
}

// ---------------------------------------------------------------------------
extern "C" void kernel_launch(void* const* d_in, const int* in_sizes, int n_in,
                              void* d_out, int out_size) {
    const float* x   = (const float*)d_in[0];
    const void*  ei  = d_in[1];
    const float* W1  = (const float*)d_in[2];
    const float* b1  = (const float*)d_in[3];
    const float* W2  = (const float*)d_in[4];
    const float* b2  = (const float*)d_in[5];
    float*       out = (float*)d_out;

    float*  hbuf = nullptr;
    float2* ws1  = nullptr;
    float2* ws2  = nullptr;
    cudaGetSymbolAddress((void**)&hbuf, g_h);
    cudaGetSymbolAddress((void**)&ws1, g_ws1);
    cudaGetSymbolAddress((void**)&ws2, g_ws2);

    const int PREP_BLOCKS = (N_NODES * F / 2 + 255) / 256;       // 6250
    const int EDGE_BLOCKS = (N_EDGES + 255) / 256;               // 3125
    const int AGG_BLOCKS  = (N_NODES + 7) / 8;                   // 6250
    const int GEMM_BLOCKS = (N_NODES + TILE_M - 1) / TILE_M;     // 391
    const int SMEM_BYTES  = (TILE_M * ROW_STRIDE) * 4 + 128 * WS_STRIDE * 8;

    cudaFuncSetAttribute(gemm_kernel,
                         cudaFuncAttributeMaxDynamicSharedMemorySize, SMEM_BYTES);

    prep_kernel<<<PREP_BLOCKS, 256>>>(ei, x, W1, W2);
    hist_kernel<<<EDGE_BLOCKS, 256>>>(ei);
    scan1_kernel<<<SCAN_BLOCKS, 256>>>();
    scan23_kernel<<<SCAN_BLOCKS, 256>>>();
    fill_kernel<<<EDGE_BLOCKS, 256>>>(ei);

    // Layer 1
    agg_kernel<<<AGG_BLOCKS, 256>>>();
    gemm_kernel<<<GEMM_BLOCKS, 256, SMEM_BYTES>>>(x, ws1, b1, hbuf,
                                                  /*relu=*/1, /*to_half=*/1);
    // Layer 2
    agg_kernel<<<AGG_BLOCKS, 256>>>();
    gemm_kernel<<<GEMM_BLOCKS, 256, SMEM_BYTES>>>(hbuf, ws2, b2, out,
                                                  /*relu=*/0, /*to_half=*/0);
}

// round 12
// speedup vs baseline: 1.2976x; 1.0026x over previous
#include <cuda_runtime.h>
#include <cuda_fp16.h>
#include <cstdint>

#define N_NODES 50000
#define N_EDGES 800000
#define F 64
#define TILE_M 128
#define ROW_STRIDE 132      // f32 stride of staged rows
#define WS_STRIDE 72        // float2 stride of W hi/lo in smem
#define SCAN_BLOCKS 196

// Scratch (allocation-free: __device__ globals)
__device__ int    g_deg[N_NODES];
__device__ int    g_off[N_NODES + 1];
__device__ int    g_cur[N_NODES];
__device__ int    g_csr[N_EDGES];
__device__ int    g_bsum[SCAN_BLOCKS];
__device__ float  g_h[N_NODES * F];
__device__ float  g_agg[N_NODES * F];
__device__ __half g_half[N_NODES * F];   // fp16 mirror of gather source
__device__ float2 g_ws1[128 * 64];       // W1 hi/lo split (3xTF32)
__device__ float2 g_ws2[128 * 64];       // W2 hi/lo split
__device__ int    g_is64;

__device__ __forceinline__ int load_idx(const void* ei, int i, int is64) {
    if (is64) return (int)((const long long*)ei)[i];
    return ((const int*)ei)[i];
}

__device__ __forceinline__ unsigned tf32_hi(float a) {
    unsigned r;
    asm("cvt.rna.tf32.f32 %0, %1;" : "=r"(r) : "f"(a));
    return r;
}

// ---------------------------------------------------------------------------
// Prep: dtype detect (thread 0 only) + zero degree + x->fp16 mirror +
// W1/W2 hi/lo split (3xTF32 precompute).
// ---------------------------------------------------------------------------
__global__ void prep_kernel(const void* __restrict__ ei,
                            const float* __restrict__ x,
                            const float* __restrict__ W1,
                            const float* __restrict__ W2) {
    int i = blockIdx.x * blockDim.x + threadIdx.x;
    if (i == 0) {
        const long long* p64 = (const long long*)ei;
        int ok = 1;
        #pragma unroll
        for (int j = 0; j < 16; j++) {
            long long v = p64[j];
            if (v < 0 || v >= N_NODES) ok = 0;
        }
        g_is64 = ok;
    }
    if (i < N_NODES) g_deg[i] = 0;
    if (i < N_NODES * F / 2) {
        float2 v = ((const float2*)x)[i];
        ((__half2*)g_half)[i] = __floats2half2_rn(v.x, v.y);
    }
    if (i < 2 * 128 * 64) {
        const float* Wsel = (i < 128 * 64) ? W1 : W2;
        float2* dst = (i < 128 * 64) ? g_ws1 : g_ws2;
        int idx = i & (128 * 64 - 1);
        float w = Wsel[idx];
        unsigned hb = tf32_hi(w);
        float hf = __uint_as_float(hb);
        unsigned lb = tf32_hi(w - hf);
        dst[idx] = make_float2(hf, __uint_as_float(lb));
    }
}

// ---------------------------------------------------------------------------
// CSR build: histogram -> scan1 -> scan23 -> fill (parallel, proven)
// ---------------------------------------------------------------------------
__global__ void hist_kernel(const void* __restrict__ ei) {
    int e = blockIdx.x * blockDim.x + threadIdx.x;
    if (e >= N_EDGES) return;
    int d = load_idx(ei, N_EDGES + e, g_is64);
    if ((unsigned)d < N_NODES) atomicAdd(&g_deg[d], 1);
}

__global__ void scan1_kernel() {
    __shared__ int sh[256];
    int t = threadIdx.x;
    int i = blockIdx.x * 256 + t;
    int v = (i < N_NODES) ? g_deg[i] : 0;
    sh[t] = v;
    __syncthreads();
    #pragma unroll
    for (int ofs = 1; ofs < 256; ofs <<= 1) {
        int add = (t >= ofs) ? sh[t - ofs] : 0;
        __syncthreads();
        sh[t] += add;
        __syncthreads();
    }
    if (i < N_NODES) g_off[i + 1] = sh[t];
    if (t == 255) g_bsum[blockIdx.x] = sh[255];
}

__global__ void scan23_kernel() {
    __shared__ int sh[256];
    int t = threadIdx.x;
    sh[t] = (t < SCAN_BLOCKS) ? g_bsum[t] : 0;
    __syncthreads();
    #pragma unroll
    for (int ofs = 1; ofs < 256; ofs <<= 1) {
        int add = (t >= ofs) ? sh[t - ofs] : 0;
        __syncthreads();
        sh[t] += add;
        __syncthreads();
    }
    int prefix = (blockIdx.x > 0) ? sh[blockIdx.x - 1] : 0;
    int i = blockIdx.x * 256 + t;
    if (i < N_NODES) {
        g_off[i + 1] += prefix;
        g_cur[i] = 0;
    }
    if (i == 0) g_off[0] = 0;
}

__global__ void fill_kernel(const void* __restrict__ ei) {
    int e = blockIdx.x * blockDim.x + threadIdx.x;
    if (e >= N_EDGES) return;
    int is64 = g_is64;
    int s = load_idx(ei, e, is64);
    int d = load_idx(ei, N_EDGES + e, is64);
    if ((unsigned)s >= N_NODES || (unsigned)d >= N_NODES) return;
    int pos = atomicAdd(&g_cur[d], 1);
    g_csr[g_off[d] + pos] = s;
}

// ---------------------------------------------------------------------------
// CSR mean-aggregation from fp16 mirror -> g_agg (f32).
// One node per warp; 4 edge-slots x 8 lanes; each lane gathers uint4
// (8 halves) -> LDG.128. Slot-strided loop, unroll-2. Final 2-round
// shfl_xor reduction across slots; lanes 0..7 store the row.
// ---------------------------------------------------------------------------
__global__ void __launch_bounds__(256)
agg_kernel() {
    int warp = threadIdx.x >> 5, lane = threadIdx.x & 31;
    int n = blockIdx.x * 8 + warp;
    if (n >= N_NODES) return;
    int slot  = lane >> 3;       // 0..3 edge slot
    int fpart = lane & 7;        // feature part (8 halves)

    const uint4* xh4 = (const uint4*)g_half;   // row = 8 x uint4

    int e0 = g_off[n], e1 = g_off[n + 1];
    float2 a0 = make_float2(0.f, 0.f), a1 = a0, a2 = a0, a3 = a0;

    int e = e0 + slot;
    for (; e + 4 < e1; e += 8) {
        int s0 = g_csr[e];
        int s1 = g_csr[e + 4];
        uint4 u0 = xh4[s0 * 8 + fpart];
        uint4 u1 = xh4[s1 * 8 + fpart];
        float2 p;
        p = __half22float2(*(__half2*)&u0.x); a0.x += p.x; a0.y += p.y;
        p = __half22float2(*(__half2*)&u0.y); a1.x += p.x; a1.y += p.y;
        p = __half22float2(*(__half2*)&u0.z); a2.x += p.x; a2.y += p.y;
        p = __half22float2(*(__half2*)&u0.w); a3.x += p.x; a3.y += p.y;
        p = __half22float2(*(__half2*)&u1.x); a0.x += p.x; a0.y += p.y;
        p = __half22float2(*(__half2*)&u1.y); a1.x += p.x; a1.y += p.y;
        p = __half22float2(*(__half2*)&u1.z); a2.x += p.x; a2.y += p.y;
        p = __half22float2(*(__half2*)&u1.w); a3.x += p.x; a3.y += p.y;
    }
    if (e < e1) {
        int s0 = g_csr[e];
        uint4 u0 = xh4[s0 * 8 + fpart];
        float2 p;
        p = __half22float2(*(__half2*)&u0.x); a0.x += p.x; a0.y += p.y;
        p = __half22float2(*(__half2*)&u0.y); a1.x += p.x; a1.y += p.y;
        p = __half22float2(*(__half2*)&u0.z); a2.x += p.x; a2.y += p.y;
        p = __half22float2(*(__half2*)&u0.w); a3.x += p.x; a3.y += p.y;
    }

    // Reduce across the 4 slots (lane bits 3 and 4).
    #pragma unroll
    for (int m = 8; m <= 16; m <<= 1) {
        a0.x += __shfl_xor_sync(0xffffffffu, a0.x, m);
        a0.y += __shfl_xor_sync(0xffffffffu, a0.y, m);
        a1.x += __shfl_xor_sync(0xffffffffu, a1.x, m);
        a1.y += __shfl_xor_sync(0xffffffffu, a1.y, m);
        a2.x += __shfl_xor_sync(0xffffffffu, a2.x, m);
        a2.y += __shfl_xor_sync(0xffffffffu, a2.y, m);
        a3.x += __shfl_xor_sync(0xffffffffu, a3.x, m);
        a3.y += __shfl_xor_sync(0xffffffffu, a3.y, m);
    }

    if (slot == 0) {
        float inv = 1.0f / fmaxf((float)(e1 - e0), 1.0f);
        float4* dst = (float4*)(g_agg + n * 64 + fpart * 8);
        dst[0] = make_float4(a0.x * inv, a0.y * inv, a1.x * inv, a1.y * inv);
        dst[1] = make_float4(a2.x * inv, a2.y * inv, a3.x * inv, a3.y * inv);
    }
}

// ---------------------------------------------------------------------------
// Tensor-core GEMM (3xTF32): out = [x || agg] @ W + b (+ReLU)
// ---------------------------------------------------------------------------
__device__ __forceinline__ void mma_tf32(float* c, unsigned a0, unsigned a1,
                                         unsigned a2, unsigned a3,
                                         unsigned b0, unsigned b1) {
    asm volatile(
        "mma.sync.aligned.m16n8k8.row.col.f32.tf32.tf32.f32 "
        "{%0,%1,%2,%3}, {%4,%5,%6,%7}, {%8,%9}, {%0,%1,%2,%3};"
        : "+f"(c[0]), "+f"(c[1]), "+f"(c[2]), "+f"(c[3])
        : "r"(a0), "r"(a1), "r"(a2), "r"(a3), "r"(b0), "r"(b1));
}

__global__ void __launch_bounds__(256)
gemm_kernel(const float* __restrict__ xin, const float2* __restrict__ Wsplit,
            const float* __restrict__ bias, float* __restrict__ out,
            int relu, int to_half) {
    extern __shared__ float sm[];
    float*  row = sm;                                   // [128][132] f32
    float2* Ws2 = (float2*)(sm + TILE_M * ROW_STRIDE);  // [128][72] (hi,lo)

    int tid = threadIdx.x;

    const float4* wsrc = (const float4*)Wsplit;
    #pragma unroll
    for (int i = 0; i < 16; i++) {
        int j = tid + i * 256;
        int f2 = j * 2;
        int k = f2 >> 6, c = f2 & 63;
        *(float4*)&Ws2[k * WS_STRIDE + c] = wsrc[j];
    }

    int base = blockIdx.x * TILE_M;
    #pragma unroll
    for (int i = 0; i < 8; i++) {
        int idx = tid + i * 256;
        int nl = idx >> 4, q = idx & 15;
        int n = base + nl;
        int nc = n < N_NODES ? n : N_NODES - 1;
        float4 xv = ((const float4*)xin)[nc * 16 + q];
        *(float4*)&row[nl * ROW_STRIDE + q * 4] = xv;
        float4 av = ((const float4*)g_agg)[nc * 16 + q];
        *(float4*)&row[nl * ROW_STRIDE + 64 + q * 4] = av;
    }
    __syncthreads();

    int warp = tid >> 5, lane = tid & 31;
    int g = lane >> 2, t = lane & 3;
    int r0 = warp * 16 + g;

    float acc[8][4];
    #pragma unroll
    for (int nt = 0; nt < 8; nt++) {
        float2 bv = ((const float2*)bias)[nt * 4 + t];
        acc[nt][0] = bv.x; acc[nt][1] = bv.y;
        acc[nt][2] = bv.x; acc[nt][3] = bv.y;
    }

    #pragma unroll 2
    for (int ks = 0; ks < 16; ks++) {
        int k0 = ks * 8;
        float a0f = row[r0 * ROW_STRIDE + k0 + t];
        float a1f = row[(r0 + 8) * ROW_STRIDE + k0 + t];
        float a2f = row[r0 * ROW_STRIDE + k0 + t + 4];
        float a3f = row[(r0 + 8) * ROW_STRIDE + k0 + t + 4];
        unsigned ah0 = tf32_hi(a0f), ah1 = tf32_hi(a1f);
        unsigned ah2 = tf32_hi(a2f), ah3 = tf32_hi(a3f);
        unsigned al0 = tf32_hi(a0f - __uint_as_float(ah0));
        unsigned al1 = tf32_hi(a1f - __uint_as_float(ah1));
        unsigned al2 = tf32_hi(a2f - __uint_as_float(ah2));
        unsigned al3 = tf32_hi(a3f - __uint_as_float(ah3));

        #pragma unroll
        for (int nt = 0; nt < 8; nt++) {
            float2 w0 = Ws2[(k0 + t)     * WS_STRIDE + nt * 8 + g];
            float2 w1 = Ws2[(k0 + t + 4) * WS_STRIDE + nt * 8 + g];
            unsigned bh0 = __float_as_uint(w0.x), bl0 = __float_as_uint(w0.y);
            unsigned bh1 = __float_as_uint(w1.x), bl1 = __float_as_uint(w1.y);
            mma_tf32(acc[nt], ah0, ah1, ah2, ah3, bh0, bh1);
            mma_tf32(acc[nt], ah0, ah1, ah2, ah3, bl0, bl1);
            mma_tf32(acc[nt], al0, al1, al2, al3, bh0, bh1);
        }
    }

    int n0 = base + r0;
    int n1 = n0 + 8;
    float2*  out2 = (float2*)out;
    __half2* oh2  = (__half2*)g_half;
    #pragma unroll
    for (int nt = 0; nt < 8; nt++) {
        float c0 = acc[nt][0], c1 = acc[nt][1];
        float c2 = acc[nt][2], c3 = acc[nt][3];
        if (relu) {
            c0 = fmaxf(c0, 0.f); c1 = fmaxf(c1, 0.f);
            c2 = fmaxf(c2, 0.f); c3 = fmaxf(c3, 0.f);
        }
        int colp = nt * 4 + t;
        if (n0 < N_NODES) {
            out2[n0 * 32 + colp] = make_float2(c0, c1);
            if (to_half) oh2[n0 * 32 + colp] = __floats2half2_rn(c0, c1);
        }
        if (n1 < N_NODES) {
            out2[n1 * 32 + colp] = make_float2(c2, c3);
            if (to_half) oh2[n1 * 32 + colp] = __floats2half2_rn(c2, c3);
        }
    }
}

// ---------------------------------------------------------------------------
extern "C" void kernel_launch(void* const* d_in, const int* in_sizes, int n_in,
                              void* d_out, int out_size) {
    const float* x   = (const float*)d_in[0];
    const void*  ei  = d_in[1];
    const float* W1  = (const float*)d_in[2];
    const float* b1  = (const float*)d_in[3];
    const float* W2  = (const float*)d_in[4];
    const float* b2  = (const float*)d_in[5];
    float*       out = (float*)d_out;

    float*  hbuf = nullptr;
    float2* ws1  = nullptr;
    float2* ws2  = nullptr;
    cudaGetSymbolAddress((void**)&hbuf, g_h);
    cudaGetSymbolAddress((void**)&ws1, g_ws1);
    cudaGetSymbolAddress((void**)&ws2, g_ws2);

    const int PREP_BLOCKS = (N_NODES * F / 2 + 255) / 256;       // 6250
    const int EDGE_BLOCKS = (N_EDGES + 255) / 256;               // 3125
    const int AGG_BLOCKS  = (N_NODES + 7) / 8;                   // 6250
    const int GEMM_BLOCKS = (N_NODES + TILE_M - 1) / TILE_M;     // 391
    const int SMEM_BYTES  = (TILE_M * ROW_STRIDE) * 4 + 128 * WS_STRIDE * 8;

    cudaFuncSetAttribute(gemm_kernel,
                         cudaFuncAttributeMaxDynamicSharedMemorySize, SMEM_BYTES);

    prep_kernel<<<PREP_BLOCKS, 256>>>(ei, x, W1, W2);
    hist_kernel<<<EDGE_BLOCKS, 256>>>(ei);
    scan1_kernel<<<SCAN_BLOCKS, 256>>>();
    scan23_kernel<<<SCAN_BLOCKS, 256>>>();
    fill_kernel<<<EDGE_BLOCKS, 256>>>(ei);

    // Layer 1
    agg_kernel<<<AGG_BLOCKS, 256>>>();
    gemm_kernel<<<GEMM_BLOCKS, 256, SMEM_BYTES>>>(x, ws1, b1, hbuf,
                                                  /*relu=*/1, /*to_half=*/1);
    // Layer 2
    agg_kernel<<<AGG_BLOCKS, 256>>>();
    gemm_kernel<<<GEMM_BLOCKS, 256, SMEM_BYTES>>>(hbuf, ws2, b2, out,
                                                  /*relu=*/0, /*to_half=*/0);
}